// round 1
// baseline (speedup 1.0000x reference)
#include <cuda_runtime.h>
#include <cuda_bf16.h>

#define NN   50000
#define DIM  128
#define NB   4
#define NR   100
#define NE   800000

// Scratch: hb = per-basis projected nodes (4 x N x 128), agg = scatter target.
__device__ float g_hb[(size_t)NB * NN * DIM];   // 102.4 MB (mostly L2-resident)
__device__ float g_agg[(size_t)NN * DIM];       // 25.6 MB

// ---------------------------------------------------------------------------
// Zero the aggregation buffer (float4 stores).
// ---------------------------------------------------------------------------
__global__ void zero_agg_kernel() {
    int i = blockIdx.x * blockDim.x + threadIdx.x;   // float4 index
    const int n4 = NN * DIM / 4;                     // 1.6M
    if (i < n4) ((float4*)g_agg)[i] = make_float4(0.f, 0.f, 0.f, 0.f);
}

// ---------------------------------------------------------------------------
// GEMM: C = h @ W for 5 weight matrices (4 bases -> g_hb, loop_weight -> out).
// Tile: 64 M x 128 N x full K=128 (two K=64 stages). 256 threads,
// each thread computes an 8x4 register tile. 48 KB static smem.
// ---------------------------------------------------------------------------
__global__ __launch_bounds__(256) void gemm_kernel(
    const float* __restrict__ h,
    const float* __restrict__ basis,
    const float* __restrict__ loopw,
    float* __restrict__ out_loop)
{
    __shared__ float As[64][64];     // [m][k] tile of h
    __shared__ float Bs[64][128];    // [k][n] tile of W

    const int mat = blockIdx.y;                       // 0..3 basis, 4 = loop
    const float* W = (mat < NB) ? basis + (size_t)mat * DIM * DIM : loopw;
    float* C       = (mat < NB) ? g_hb  + (size_t)mat * NN * DIM  : out_loop;

    const int m0   = blockIdx.x * 64;
    const int tid  = threadIdx.x;
    const int warp = tid >> 5;
    const int lane = tid & 31;
    const int mbase = warp * 8;     // 8 warps cover 64 M rows
    const int nbase = lane * 4;     // 32 lanes cover 128 N cols

    float acc[8][4];
    #pragma unroll
    for (int i = 0; i < 8; i++)
        #pragma unroll
        for (int j = 0; j < 4; j++) acc[i][j] = 0.f;

    for (int kt = 0; kt < DIM; kt += 64) {
        // Load A tile: 64 rows x 64 cols = 1024 float4, 4 per thread.
        #pragma unroll
        for (int i = 0; i < 4; i++) {
            int idx = tid + i * 256;          // 0..1023
            int row = idx >> 4;               // 16 float4 per row
            int c4  = idx & 15;
            int m   = m0 + row;
            float4 v = make_float4(0.f, 0.f, 0.f, 0.f);
            if (m < NN) v = *(const float4*)(h + (size_t)m * DIM + kt + c4 * 4);
            *(float4*)&As[row][c4 * 4] = v;
        }
        // Load B tile: 64 rows x 128 cols = 2048 float4, 8 per thread.
        #pragma unroll
        for (int i = 0; i < 8; i++) {
            int idx = tid + i * 256;          // 0..2047
            int row = idx >> 5;               // 32 float4 per row
            int c4  = idx & 31;
            *(float4*)&Bs[row][c4 * 4] =
                *(const float4*)(W + (size_t)(kt + row) * DIM + c4 * 4);
        }
        __syncthreads();

        #pragma unroll 4
        for (int k = 0; k < 64; k += 4) {
            float4 b0 = *(float4*)&Bs[k    ][nbase];
            float4 b1 = *(float4*)&Bs[k + 1][nbase];
            float4 b2 = *(float4*)&Bs[k + 2][nbase];
            float4 b3 = *(float4*)&Bs[k + 3][nbase];
            #pragma unroll
            for (int i = 0; i < 8; i++) {
                float4 a = *(float4*)&As[mbase + i][k];   // warp-broadcast
                acc[i][0] = fmaf(a.x, b0.x, fmaf(a.y, b1.x, fmaf(a.z, b2.x, fmaf(a.w, b3.x, acc[i][0]))));
                acc[i][1] = fmaf(a.x, b0.y, fmaf(a.y, b1.y, fmaf(a.z, b2.y, fmaf(a.w, b3.y, acc[i][1]))));
                acc[i][2] = fmaf(a.x, b0.z, fmaf(a.y, b1.z, fmaf(a.z, b2.z, fmaf(a.w, b3.z, acc[i][2]))));
                acc[i][3] = fmaf(a.x, b0.w, fmaf(a.y, b1.w, fmaf(a.z, b2.w, fmaf(a.w, b3.w, acc[i][3]))));
            }
        }
        __syncthreads();
    }

    #pragma unroll
    for (int i = 0; i < 8; i++) {
        int m = m0 + mbase + i;
        if (m < NN)
            *(float4*)(C + (size_t)m * DIM + nbase) =
                make_float4(acc[i][0], acc[i][1], acc[i][2], acc[i][3]);
    }
}

// ---------------------------------------------------------------------------
// Edge kernel: one warp per edge.
//   msg = sum_b coeff[rel][b] * hb[b][src]   (128 floats, 4 per lane)
//   agg[dst] += msg  via red.global.add.v4.f32 (no return, vectorized)
// ---------------------------------------------------------------------------
__global__ __launch_bounds__(256) void edge_kernel(
    const int* __restrict__ src,
    const int* __restrict__ dst,
    const int* __restrict__ rel,
    const float* __restrict__ coeff)
{
    int e    = (blockIdx.x * blockDim.x + threadIdx.x) >> 5;
    int lane = threadIdx.x & 31;
    if (e >= NE) return;

    int s = __ldg(&src[e]);
    int d = __ldg(&dst[e]);
    int r = __ldg(&rel[e]);
    float4 c = *(const float4*)(coeff + r * 4);   // 16B-aligned row

    const float4* hb4 = (const float4*)g_hb;
    const size_t stride = (size_t)NN * 32;        // one basis block, in float4
    size_t base = (size_t)s * 32 + lane;

    float4 v0 = hb4[base];
    float4 v1 = hb4[base + stride];
    float4 v2 = hb4[base + 2 * stride];
    float4 v3 = hb4[base + 3 * stride];

    float4 m;
    m.x = fmaf(c.x, v0.x, fmaf(c.y, v1.x, fmaf(c.z, v2.x, c.w * v3.x)));
    m.y = fmaf(c.x, v0.y, fmaf(c.y, v1.y, fmaf(c.z, v2.y, c.w * v3.y)));
    m.z = fmaf(c.x, v0.z, fmaf(c.y, v1.z, fmaf(c.z, v2.z, c.w * v3.z)));
    m.w = fmaf(c.x, v0.w, fmaf(c.y, v1.w, fmaf(c.z, v2.w, c.w * v3.w)));

    float* outp = g_agg + (size_t)d * DIM + lane * 4;
    asm volatile("red.global.add.v4.f32 [%0], {%1, %2, %3, %4};"
                 :: "l"(outp), "f"(m.x), "f"(m.y), "f"(m.z), "f"(m.w)
                 : "memory");
}

// ---------------------------------------------------------------------------
// Epilogue: out = relu(agg * norm + loop_message)   (loop_message already in out)
// ---------------------------------------------------------------------------
__global__ void final_kernel(const float* __restrict__ norm, float* __restrict__ out) {
    int i = blockIdx.x * blockDim.x + threadIdx.x;   // float4 index
    const int n4 = NN * DIM / 4;
    if (i >= n4) return;
    int node = i >> 5;                                // 32 float4 per node row
    float nm = __ldg(&norm[node]);
    float4 a = ((const float4*)g_agg)[i];
    float4 o = ((float4*)out)[i];
    o.x = fmaxf(fmaf(a.x, nm, o.x), 0.f);
    o.y = fmaxf(fmaf(a.y, nm, o.y), 0.f);
    o.z = fmaxf(fmaf(a.z, nm, o.z), 0.f);
    o.w = fmaxf(fmaf(a.w, nm, o.w), 0.f);
    ((float4*)out)[i] = o;
}

// ---------------------------------------------------------------------------
extern "C" void kernel_launch(void* const* d_in, const int* in_sizes, int n_in,
                              void* d_out, int out_size) {
    const float* h     = (const float*)d_in[0];
    const float* norm  = (const float*)d_in[1];
    const int*   src   = (const int*)  d_in[2];
    const int*   dst   = (const int*)  d_in[3];
    const int*   rel   = (const int*)  d_in[4];
    const float* basis = (const float*)d_in[5];
    const float* coeff = (const float*)d_in[6];
    const float* loopw = (const float*)d_in[7];
    float* out = (float*)d_out;

    zero_agg_kernel<<<(NN * DIM / 4 + 255) / 256, 256>>>();

    dim3 gg((NN + 63) / 64, NB + 1);
    gemm_kernel<<<gg, 256>>>(h, basis, loopw, out);

    edge_kernel<<<(NE * 32) / 256, 256>>>(src, dst, rel, coeff);

    final_kernel<<<(NN * DIM / 4 + 255) / 256, 256>>>(norm, out);
}

// round 4
// speedup vs baseline: 1.0013x; 1.0013x over previous
#include <cuda_runtime.h>
#include <cuda_bf16.h>

#define NN   50000
#define DIM  128
#define NB   4
#define NR   100
#define NE   800000

// Scratch: hb = per-basis projected nodes (4 x N x 128), agg = scatter target.
__device__ float g_hb[(size_t)NB * NN * DIM];   // 102.4 MB (mostly L2-resident)
__device__ float g_agg[(size_t)NN * DIM];       // 25.6 MB

// Packed fp32x2 helpers (sm_103a FFMA2 path — 2 fp32 FMAs per instruction).
#define FMA2(acc, a, b) \
    asm("fma.rn.f32x2 %0, %1, %2, %0;" : "+l"(acc) : "l"(a), "l"(b))
#define BCAST2(dst, f) \
    asm("mov.b64 %0, {%1, %1};" : "=l"(dst) : "f"(f))
#define UNPACK2(lo, hi, p) \
    asm("mov.b64 {%0, %1}, %2;" : "=f"(lo), "=f"(hi) : "l"(p))

// ---------------------------------------------------------------------------
// Zero the aggregation buffer (float4 stores).
// ---------------------------------------------------------------------------
__global__ void zero_agg_kernel() {
    int i = blockIdx.x * blockDim.x + threadIdx.x;   // float4 index
    const int n4 = NN * DIM / 4;                     // 1.6M
    if (i < n4) ((float4*)g_agg)[i] = make_float4(0.f, 0.f, 0.f, 0.f);
}

// ---------------------------------------------------------------------------
// GEMM: C = h @ W for 5 weight matrices (4 bases -> g_hb, loop_weight -> out).
// Tile: 64 M x 128 N, K in two 64-wide stages. 256 threads; each thread owns
// an 8(M) x 4(N) register tile held as 8 x 2 packed f32x2 accumulators.
// Inner loop uses fma.rn.f32x2 -> half the fma-pipe instructions of FFMA.
// ---------------------------------------------------------------------------
__global__ __launch_bounds__(256) void gemm_kernel(
    const float* __restrict__ h,
    const float* __restrict__ basis,
    const float* __restrict__ loopw,
    float* __restrict__ out_loop)
{
    __shared__ float As[64][64];     // [m][k] tile of h
    __shared__ float Bs[64][128];    // [k][n] tile of W

    const int mat = blockIdx.y;                       // 0..3 basis, 4 = loop
    const float* W = (mat < NB) ? basis + (size_t)mat * DIM * DIM : loopw;
    float* C       = (mat < NB) ? g_hb  + (size_t)mat * NN * DIM  : out_loop;

    const int m0   = blockIdx.x * 64;
    const int tid  = threadIdx.x;
    const int warp = tid >> 5;
    const int lane = tid & 31;
    const int mbase = warp * 8;     // 8 warps cover 64 M rows
    const int nbase = lane * 4;     // 32 lanes cover 128 N cols

    unsigned long long acc[8][2];   // [m][npair]: lo = n, hi = n+1
    #pragma unroll
    for (int i = 0; i < 8; i++) { acc[i][0] = 0ull; acc[i][1] = 0ull; }

    for (int kt = 0; kt < DIM; kt += 64) {
        // Load A tile: 64 rows x 64 cols = 1024 float4, 4 per thread.
        #pragma unroll
        for (int i = 0; i < 4; i++) {
            int idx = tid + i * 256;          // 0..1023
            int row = idx >> 4;               // 16 float4 per row
            int c4  = idx & 15;
            int m   = m0 + row;
            float4 v = make_float4(0.f, 0.f, 0.f, 0.f);
            if (m < NN) v = *(const float4*)(h + (size_t)m * DIM + kt + c4 * 4);
            *(float4*)&As[row][c4 * 4] = v;
        }
        // Load B tile: 64 rows x 128 cols = 2048 float4, 8 per thread.
        #pragma unroll
        for (int i = 0; i < 8; i++) {
            int idx = tid + i * 256;          // 0..2047
            int row = idx >> 5;               // 32 float4 per row
            int c4  = idx & 31;
            *(float4*)&Bs[row][c4 * 4] =
                *(const float4*)(W + (size_t)(kt + row) * DIM + c4 * 4);
        }
        __syncthreads();

        #pragma unroll 4
        for (int k = 0; k < 64; k += 4) {
            // B rows k..k+3, 4 cols each = 2 packed f32x2 per row.
            ulonglong2 B0 = *(ulonglong2*)&Bs[k    ][nbase];
            ulonglong2 B1 = *(ulonglong2*)&Bs[k + 1][nbase];
            ulonglong2 B2 = *(ulonglong2*)&Bs[k + 2][nbase];
            ulonglong2 B3 = *(ulonglong2*)&Bs[k + 3][nbase];
            #pragma unroll
            for (int i = 0; i < 8; i++) {
                float4 a = *(float4*)&As[mbase + i][k];   // warp-broadcast
                unsigned long long a2;
                BCAST2(a2, a.x);
                FMA2(acc[i][0], a2, B0.x); FMA2(acc[i][1], a2, B0.y);
                BCAST2(a2, a.y);
                FMA2(acc[i][0], a2, B1.x); FMA2(acc[i][1], a2, B1.y);
                BCAST2(a2, a.z);
                FMA2(acc[i][0], a2, B2.x); FMA2(acc[i][1], a2, B2.y);
                BCAST2(a2, a.w);
                FMA2(acc[i][0], a2, B3.x); FMA2(acc[i][1], a2, B3.y);
            }
        }
        __syncthreads();
    }

    #pragma unroll
    for (int i = 0; i < 8; i++) {
        int m = m0 + mbase + i;
        if (m < NN) {
            float4 o;
            UNPACK2(o.x, o.y, acc[i][0]);
            UNPACK2(o.z, o.w, acc[i][1]);
            *(float4*)(C + (size_t)m * DIM + nbase) = o;
        }
    }
}

// ---------------------------------------------------------------------------
// Edge kernel: one warp per edge.
//   msg = sum_b coeff[rel][b] * hb[b][src]   (128 floats, 4 per lane)
//   agg[dst] += msg  via red.global.add.v4.f32 (no return, vectorized)
// ---------------------------------------------------------------------------
__global__ __launch_bounds__(256) void edge_kernel(
    const int* __restrict__ src,
    const int* __restrict__ dst,
    const int* __restrict__ rel,
    const float* __restrict__ coeff)
{
    int e    = (blockIdx.x * blockDim.x + threadIdx.x) >> 5;
    int lane = threadIdx.x & 31;
    if (e >= NE) return;

    int s = __ldg(&src[e]);
    int d = __ldg(&dst[e]);
    int r = __ldg(&rel[e]);
    float4 c = *(const float4*)(coeff + r * 4);   // 16B-aligned row

    const float4* hb4 = (const float4*)g_hb;
    const size_t stride = (size_t)NN * 32;        // one basis block, in float4
    size_t base = (size_t)s * 32 + lane;

    float4 v0 = hb4[base];
    float4 v1 = hb4[base + stride];
    float4 v2 = hb4[base + 2 * stride];
    float4 v3 = hb4[base + 3 * stride];

    float4 m;
    m.x = fmaf(c.x, v0.x, fmaf(c.y, v1.x, fmaf(c.z, v2.x, c.w * v3.x)));
    m.y = fmaf(c.x, v0.y, fmaf(c.y, v1.y, fmaf(c.z, v2.y, c.w * v3.y)));
    m.z = fmaf(c.x, v0.z, fmaf(c.y, v1.z, fmaf(c.z, v2.z, c.w * v3.z)));
    m.w = fmaf(c.x, v0.w, fmaf(c.y, v1.w, fmaf(c.z, v2.w, c.w * v3.w)));

    float* outp = g_agg + (size_t)d * DIM + lane * 4;
    asm volatile("red.global.add.v4.f32 [%0], {%1, %2, %3, %4};"
                 :: "l"(outp), "f"(m.x), "f"(m.y), "f"(m.z), "f"(m.w)
                 : "memory");
}

// ---------------------------------------------------------------------------
// Epilogue: out = relu(agg * norm + loop_message)   (loop_message already in out)
// ---------------------------------------------------------------------------
__global__ void final_kernel(const float* __restrict__ norm, float* __restrict__ out) {
    int i = blockIdx.x * blockDim.x + threadIdx.x;   // float4 index
    const int n4 = NN * DIM / 4;
    if (i >= n4) return;
    int node = i >> 5;                                // 32 float4 per node row
    float nm = __ldg(&norm[node]);
    float4 a = ((const float4*)g_agg)[i];
    float4 o = ((float4*)out)[i];
    o.x = fmaxf(fmaf(a.x, nm, o.x), 0.f);
    o.y = fmaxf(fmaf(a.y, nm, o.y), 0.f);
    o.z = fmaxf(fmaf(a.z, nm, o.z), 0.f);
    o.w = fmaxf(fmaf(a.w, nm, o.w), 0.f);
    ((float4*)out)[i] = o;
}

// ---------------------------------------------------------------------------
extern "C" void kernel_launch(void* const* d_in, const int* in_sizes, int n_in,
                              void* d_out, int out_size) {
    const float* h     = (const float*)d_in[0];
    const float* norm  = (const float*)d_in[1];
    const int*   src   = (const int*)  d_in[2];
    const int*   dst   = (const int*)  d_in[3];
    const int*   rel   = (const int*)  d_in[4];
    const float* basis = (const float*)d_in[5];
    const float* coeff = (const float*)d_in[6];
    const float* loopw = (const float*)d_in[7];
    float* out = (float*)d_out;

    zero_agg_kernel<<<(NN * DIM / 4 + 255) / 256, 256>>>();

    dim3 gg((NN + 63) / 64, NB + 1);
    gemm_kernel<<<gg, 256>>>(h, basis, loopw, out);

    edge_kernel<<<(NE * 32) / 256, 256>>>(src, dst, rel, coeff);

    final_kernel<<<(NN * DIM / 4 + 255) / 256, 256>>>(norm, out);
}

// round 11
// speedup vs baseline: 1.1491x; 1.1476x over previous
#include <cuda_runtime.h>
#include <cuda_bf16.h>
#include <mma.h>
#include <cstdint>

using namespace nvcuda;

#define NN     50000
#define NN_PAD 50048                 // 391 * 128, padded so GEMM tiles need no guards
#define DIM    128
#define NB     4
#define NR     100
#define NE     800000
#define NMAT   5                     // 4 bases + loop
#define MTILES 391                   // NN_PAD / 128

// ---------------------------------------------------------------------------
// Device scratch (zero-initialized at module load; tails never written ->
// stay zero, so padded rows are benign).
// ---------------------------------------------------------------------------
__device__ float g_hb[(size_t)NB * NN_PAD * DIM];        // 102.5 MB
__device__ float g_loop[(size_t)NN_PAD * DIM];           // 25.6 MB (self-loop msg)
__device__ float g_agg[(size_t)NN * DIM];                // 25.6 MB
__device__ __nv_bfloat16 g_h1[(size_t)NN_PAD * DIM];     // bf16 limbs of h
__device__ __nv_bfloat16 g_h2[(size_t)NN_PAD * DIM];
// W^T limbs: [mat][limb][n][k] bf16 (n-major, so wmma col_major B works)
__device__ __nv_bfloat16 g_wt[(size_t)NMAT * 2 * DIM * DIM];

// ---------------------------------------------------------------------------
// bf16x2 split of h:  x = b1 + b2 + O(2^-18 x)
// ---------------------------------------------------------------------------
__global__ void split_h_kernel(const float* __restrict__ h) {
    int i = blockIdx.x * blockDim.x + threadIdx.x;
    if (i >= NN * DIM) return;
    float x = h[i];
    __nv_bfloat16 b1 = __float2bfloat16(x);
    float r1 = x - __bfloat162float(b1);
    g_h1[i] = b1;
    g_h2[i] = __float2bfloat16(r1);
}

// bf16x2 split of W, transposed to [n][k]
__global__ void split_w_kernel(const float* __restrict__ basis,
                               const float* __restrict__ loopw) {
    int i = blockIdx.x * blockDim.x + threadIdx.x;   // over NMAT*DIM*DIM
    if (i >= NMAT * DIM * DIM) return;
    int mat = i / (DIM * DIM);
    int rem = i - mat * DIM * DIM;
    int n = rem / DIM, k = rem - (rem / DIM) * DIM;
    float x = (mat < NB) ? basis[(size_t)mat * DIM * DIM + k * DIM + n]
                         : loopw[k * DIM + n];
    __nv_bfloat16 b1 = __float2bfloat16(x);
    float r1 = x - __bfloat162float(b1);
    size_t base = (size_t)mat * 2 * DIM * DIM + (size_t)n * DIM + k;
    g_wt[base]             = b1;
    g_wt[base + DIM * DIM] = __float2bfloat16(r1);
}

// ---------------------------------------------------------------------------
// wmma bf16 GEMM: one CTA = 128x128 tile of C = h @ W.
// 3 limb products (a1w1, a1w2, a2w1) accumulated in fp32 frags.
// 8 warps in a 4x2 grid; warp tile 32(M) x 64(N). K=128 fully SMEM-resident.
// ---------------------------------------------------------------------------
#define SM_STRIDE 136                 // 128 + 8 bf16 pad (272 B rows, LDSM-friendly)
#define SM_LIMB   (128 * SM_STRIDE)   // elements per limb tile
#define SM_TOTAL  (4 * SM_LIMB * 2)   // bytes: A limbs (2) + B limbs (2) = 139264

__global__ void __launch_bounds__(256, 1) gemm_wmma_kernel() {
    extern __shared__ __nv_bfloat16 smem[];
    __nv_bfloat16* As = smem;                 // [2][128][SM_STRIDE]
    __nv_bfloat16* Bs = smem + 2 * SM_LIMB;   // [2][128][SM_STRIDE]

    const int tid = threadIdx.x;
    const int wid = tid >> 5;
    const int mat = blockIdx.y;
    const int m0  = blockIdx.x * 128;
    float* C = (mat < NB) ? g_hb + (size_t)mat * NN_PAD * DIM : g_loop;

    // ---- Load A limbs (128 rows x 128 bf16 each), no bounds checks (padded).
    {
        const __nv_bfloat16* hs[2] = { g_h1, g_h2 };
        #pragma unroll
        for (int s = 0; s < 2; s++) {
            const __nv_bfloat16* src = hs[s] + (size_t)m0 * DIM;
            __nv_bfloat16* dst = As + s * SM_LIMB;
            #pragma unroll
            for (int it = 0; it < 8; it++) {
                int idx = it * 256 + tid;         // 0..2047 16B chunks
                int row = idx >> 4;
                int c8  = (idx & 15) * 8;
                *(float4*)(dst + row * SM_STRIDE + c8) =
                    *(const float4*)(src + row * DIM + c8);
            }
        }
        // ---- Load B limbs (W^T, 128 n-rows x 128 k).
        const __nv_bfloat16* wb = g_wt + (size_t)mat * 2 * DIM * DIM;
        #pragma unroll
        for (int s = 0; s < 2; s++) {
            const __nv_bfloat16* src = wb + (size_t)s * DIM * DIM;
            __nv_bfloat16* dst = Bs + s * SM_LIMB;
            #pragma unroll
            for (int it = 0; it < 8; it++) {
                int idx = it * 256 + tid;
                int row = idx >> 4;
                int c8  = (idx & 15) * 8;
                *(float4*)(dst + row * SM_STRIDE + c8) =
                    *(const float4*)(src + row * DIM + c8);
            }
        }
    }
    __syncthreads();

    const int wm = (wid >> 1) * 32;   // warp M origin (0,32,64,96)
    const int wn = (wid & 1) * 64;    // warp N origin (0,64)

    wmma::fragment<wmma::accumulator, 16, 16, 16, float> acc[2][4];
    #pragma unroll
    for (int i = 0; i < 2; i++)
        #pragma unroll
        for (int j = 0; j < 4; j++) wmma::fill_fragment(acc[i][j], 0.0f);

    const int pa[3] = {0, 0, 1};
    const int pb[3] = {0, 1, 0};
    #pragma unroll
    for (int p = 0; p < 3; p++) {
        const __nv_bfloat16* Ab = As + pa[p] * SM_LIMB;
        const __nv_bfloat16* Bb = Bs + pb[p] * SM_LIMB;
        #pragma unroll
        for (int k = 0; k < DIM; k += 16) {
            wmma::fragment<wmma::matrix_a, 16, 16, 16, __nv_bfloat16, wmma::row_major> af[2];
            wmma::load_matrix_sync(af[0], Ab + (wm     ) * SM_STRIDE + k, SM_STRIDE);
            wmma::load_matrix_sync(af[1], Ab + (wm + 16) * SM_STRIDE + k, SM_STRIDE);
            #pragma unroll
            for (int j = 0; j < 4; j++) {
                wmma::fragment<wmma::matrix_b, 16, 16, 16, __nv_bfloat16, wmma::col_major> bf;
                // col_major: element (k, n) at ptr[n * ldm + k]; Bs is [n][k].
                wmma::load_matrix_sync(bf, Bb + (wn + j * 16) * SM_STRIDE + k, SM_STRIDE);
                wmma::mma_sync(acc[0][j], af[0], bf, acc[0][j]);
                wmma::mma_sync(acc[1][j], af[1], bf, acc[1][j]);
            }
        }
    }

    // ---- Store (C padded: no guards).
    #pragma unroll
    for (int i = 0; i < 2; i++)
        #pragma unroll
        for (int j = 0; j < 4; j++)
            wmma::store_matrix_sync(C + (size_t)(m0 + wm + i * 16) * DIM + wn + j * 16,
                                    acc[i][j], DIM, wmma::mem_row_major);
}

// ---------------------------------------------------------------------------
// Zero the aggregation buffer.
// ---------------------------------------------------------------------------
__global__ void zero_agg_kernel() {
    int i = blockIdx.x * blockDim.x + threadIdx.x;
    const int n4 = NN * DIM / 4;
    if (i < n4) ((float4*)g_agg)[i] = make_float4(0.f, 0.f, 0.f, 0.f);
}

// ---------------------------------------------------------------------------
// Edge kernel: one warp per edge; red.global.add.v4.f32 scatter.
// ---------------------------------------------------------------------------
__global__ __launch_bounds__(256) void edge_kernel(
    const int* __restrict__ src, const int* __restrict__ dst,
    const int* __restrict__ rel, const float* __restrict__ coeff)
{
    int e    = (blockIdx.x * blockDim.x + threadIdx.x) >> 5;
    int lane = threadIdx.x & 31;
    if (e >= NE) return;

    int s = __ldg(&src[e]);
    int d = __ldg(&dst[e]);
    int r = __ldg(&rel[e]);
    float4 c = *(const float4*)(coeff + r * 4);

    const float4* hb4 = (const float4*)g_hb;
    const size_t stride = (size_t)NN_PAD * 32;    // one basis block, in float4
    size_t base = (size_t)s * 32 + lane;

    float4 v0 = hb4[base];
    float4 v1 = hb4[base + stride];
    float4 v2 = hb4[base + 2 * stride];
    float4 v3 = hb4[base + 3 * stride];

    float4 m;
    m.x = fmaf(c.x, v0.x, fmaf(c.y, v1.x, fmaf(c.z, v2.x, c.w * v3.x)));
    m.y = fmaf(c.x, v0.y, fmaf(c.y, v1.y, fmaf(c.z, v2.y, c.w * v3.y)));
    m.z = fmaf(c.x, v0.z, fmaf(c.y, v1.z, fmaf(c.z, v2.z, c.w * v3.z)));
    m.w = fmaf(c.x, v0.w, fmaf(c.y, v1.w, fmaf(c.z, v2.w, c.w * v3.w)));

    float* outp = g_agg + (size_t)d * DIM + lane * 4;
    asm volatile("red.global.add.v4.f32 [%0], {%1, %2, %3, %4};"
                 :: "l"(outp), "f"(m.x), "f"(m.y), "f"(m.z), "f"(m.w) : "memory");
}

// ---------------------------------------------------------------------------
// Epilogue: out = relu(agg * norm + loop_message)
// ---------------------------------------------------------------------------
__global__ void final_kernel(const float* __restrict__ norm, float* __restrict__ out) {
    int i = blockIdx.x * blockDim.x + threadIdx.x;   // float4 index
    const int n4 = NN * DIM / 4;
    if (i >= n4) return;
    int node = i >> 5;
    float nm = __ldg(&norm[node]);
    float4 a = ((const float4*)g_agg)[i];
    float4 l = ((const float4*)g_loop)[i];
    float4 o;
    o.x = fmaxf(fmaf(a.x, nm, l.x), 0.f);
    o.y = fmaxf(fmaf(a.y, nm, l.y), 0.f);
    o.z = fmaxf(fmaf(a.z, nm, l.z), 0.f);
    o.w = fmaxf(fmaf(a.w, nm, l.w), 0.f);
    ((float4*)out)[i] = o;
}

// ---------------------------------------------------------------------------
extern "C" void kernel_launch(void* const* d_in, const int* in_sizes, int n_in,
                              void* d_out, int out_size) {
    const float* h     = (const float*)d_in[0];
    const float* norm  = (const float*)d_in[1];
    const int*   src   = (const int*)  d_in[2];
    const int*   dst   = (const int*)  d_in[3];
    const int*   rel   = (const int*)  d_in[4];
    const float* basis = (const float*)d_in[5];
    const float* coeff = (const float*)d_in[6];
    const float* loopw = (const float*)d_in[7];
    float* out = (float*)d_out;

    // Sticky attribute: set once, outside any captured work. Deterministic.
    static bool attr_done = false;
    if (!attr_done) {
        cudaFuncSetAttribute(gemm_wmma_kernel,
                             cudaFuncAttributeMaxDynamicSharedMemorySize, SM_TOTAL);
        attr_done = true;
    }

    split_h_kernel<<<(NN * DIM + 255) / 256, 256>>>(h);
    split_w_kernel<<<(NMAT * DIM * DIM + 255) / 256, 256>>>(basis, loopw);
    zero_agg_kernel<<<(NN * DIM / 4 + 255) / 256, 256>>>();

    dim3 gg(MTILES, NMAT);
    gemm_wmma_kernel<<<gg, 256, SM_TOTAL>>>();

    edge_kernel<<<(NE * 32) / 256, 256>>>(src, dst, rel, coeff);

    final_kernel<<<(NN * DIM / 4 + 255) / 256, 256>>>(norm, out);
}

// round 12
// speedup vs baseline: 1.1754x; 1.0229x over previous
#include <cuda_runtime.h>
#include <cuda_bf16.h>
#include <mma.h>
#include <cstdint>

using namespace nvcuda;

#define NN     50000
#define NN_PAD 50048                 // 391 * 128, padded so GEMM tiles need no guards
#define DIM    128
#define NB     4
#define NR     100
#define NE     800000
#define NMAT   5                     // 4 bases + loop
#define MTILES 782                   // NN_PAD / 64

// ---------------------------------------------------------------------------
// Device scratch (zero-initialized at module load; padded tails stay zero).
// ---------------------------------------------------------------------------
__device__ float g_hb[(size_t)NB * NN_PAD * DIM];        // 102.5 MB
__device__ float g_loop[(size_t)NN_PAD * DIM];           // 25.6 MB (self-loop msg)
__device__ float g_agg[(size_t)NN * DIM];                // 25.6 MB
__device__ __nv_bfloat16 g_h1[(size_t)NN_PAD * DIM];     // bf16 limbs of h
__device__ __nv_bfloat16 g_h2[(size_t)NN_PAD * DIM];
// W^T limbs: [mat][limb][n][k] bf16 (n-major, so wmma col_major B works)
__device__ __nv_bfloat16 g_wt[(size_t)NMAT * 2 * DIM * DIM];

// ---------------------------------------------------------------------------
// bf16x2 split of h:  x = b1 + b2 + O(2^-18 x)
// ---------------------------------------------------------------------------
__global__ void split_h_kernel(const float* __restrict__ h) {
    int i = blockIdx.x * blockDim.x + threadIdx.x;
    if (i >= NN * DIM) return;
    float x = h[i];
    __nv_bfloat16 b1 = __float2bfloat16(x);
    float r1 = x - __bfloat162float(b1);
    g_h1[i] = b1;
    g_h2[i] = __float2bfloat16(r1);
}

// bf16x2 split of W, transposed to [n][k]
__global__ void split_w_kernel(const float* __restrict__ basis,
                               const float* __restrict__ loopw) {
    int i = blockIdx.x * blockDim.x + threadIdx.x;   // over NMAT*DIM*DIM
    if (i >= NMAT * DIM * DIM) return;
    int mat = i / (DIM * DIM);
    int rem = i - mat * DIM * DIM;
    int n = rem / DIM, k = rem - (rem / DIM) * DIM;
    float x = (mat < NB) ? basis[(size_t)mat * DIM * DIM + k * DIM + n]
                         : loopw[k * DIM + n];
    __nv_bfloat16 b1 = __float2bfloat16(x);
    float r1 = x - __bfloat162float(b1);
    size_t base = (size_t)mat * 2 * DIM * DIM + (size_t)n * DIM + k;
    g_wt[base]             = b1;
    g_wt[base + DIM * DIM] = __float2bfloat16(r1);
}

// ---------------------------------------------------------------------------
// wmma bf16 GEMM: one CTA = 64x128 tile of C = h @ W.
// bf16x2 limbs; per k-step the 3 significant products (a1w1, a1w2, a2w1)
// are issued from freshly loaded frags -> small live set, no spills.
// 8 warps in a 2x4 grid; warp tile 32(M) x 32(N). K=128 SMEM-resident.
// smem 104.4 KB -> 2 CTAs/SM (16 warps).
// ---------------------------------------------------------------------------
#define SM_STRIDE 136                      // 128 + 8 bf16 pad
#define SM_A_LIMB (64 * SM_STRIDE)         // elements per A limb tile
#define SM_B_LIMB (128 * SM_STRIDE)        // elements per B limb tile
#define SM_TOTAL  ((2 * SM_A_LIMB + 2 * SM_B_LIMB) * 2)   // 104448 bytes

__global__ void __launch_bounds__(256, 2) gemm_wmma_kernel() {
    extern __shared__ __nv_bfloat16 smem[];
    __nv_bfloat16* As = smem;                   // [2][64][SM_STRIDE]
    __nv_bfloat16* Bs = smem + 2 * SM_A_LIMB;   // [2][128][SM_STRIDE]

    const int tid = threadIdx.x;
    const int wid = tid >> 5;
    const int mat = blockIdx.y;
    const int m0  = blockIdx.x * 64;
    float* C = (mat < NB) ? g_hb + (size_t)mat * NN_PAD * DIM : g_loop;

    // ---- Load A limbs (64 rows x 128 bf16 each); padded, no guards.
    {
        const __nv_bfloat16* hs[2] = { g_h1, g_h2 };
        #pragma unroll
        for (int s = 0; s < 2; s++) {
            const __nv_bfloat16* src = hs[s] + (size_t)m0 * DIM;
            __nv_bfloat16* dst = As + s * SM_A_LIMB;
            #pragma unroll
            for (int it = 0; it < 4; it++) {
                int idx = it * 256 + tid;         // 0..1023 16B chunks
                int row = idx >> 4;
                int c8  = (idx & 15) * 8;
                *(float4*)(dst + row * SM_STRIDE + c8) =
                    *(const float4*)(src + row * DIM + c8);
            }
        }
        // ---- Load B limbs (W^T, 128 n-rows x 128 k).
        const __nv_bfloat16* wb = g_wt + (size_t)mat * 2 * DIM * DIM;
        #pragma unroll
        for (int s = 0; s < 2; s++) {
            const __nv_bfloat16* src = wb + (size_t)s * DIM * DIM;
            __nv_bfloat16* dst = Bs + s * SM_B_LIMB;
            #pragma unroll
            for (int it = 0; it < 8; it++) {
                int idx = it * 256 + tid;         // 0..2047
                int row = idx >> 4;
                int c8  = (idx & 15) * 8;
                *(float4*)(dst + row * SM_STRIDE + c8) =
                    *(const float4*)(src + row * DIM + c8);
            }
        }
    }
    __syncthreads();

    const int wm = (wid >> 2) * 32;   // warp M origin (0, 32)
    const int wn = (wid & 3) * 32;    // warp N origin (0, 32, 64, 96)

    wmma::fragment<wmma::accumulator, 16, 16, 16, float> acc[2][2];
    #pragma unroll
    for (int i = 0; i < 2; i++)
        #pragma unroll
        for (int j = 0; j < 2; j++) wmma::fill_fragment(acc[i][j], 0.0f);

    #pragma unroll 2
    for (int k = 0; k < DIM; k += 16) {
        // A frags: [limb][m-sub]
        wmma::fragment<wmma::matrix_a, 16, 16, 16, __nv_bfloat16, wmma::row_major> af[2][2];
        #pragma unroll
        for (int s = 0; s < 2; s++) {
            wmma::load_matrix_sync(af[s][0], As + s * SM_A_LIMB + (wm     ) * SM_STRIDE + k, SM_STRIDE);
            wmma::load_matrix_sync(af[s][1], As + s * SM_A_LIMB + (wm + 16) * SM_STRIDE + k, SM_STRIDE);
        }
        // B frags: [limb][n-sub] (col_major: element (k, n) at ptr[n*ldm + k])
        wmma::fragment<wmma::matrix_b, 16, 16, 16, __nv_bfloat16, wmma::col_major> bf[2][2];
        #pragma unroll
        for (int s = 0; s < 2; s++) {
            wmma::load_matrix_sync(bf[s][0], Bs + s * SM_B_LIMB + (wn     ) * SM_STRIDE + k, SM_STRIDE);
            wmma::load_matrix_sync(bf[s][1], Bs + s * SM_B_LIMB + (wn + 16) * SM_STRIDE + k, SM_STRIDE);
        }
        // 3 significant limb products per (mi, nj)
        #pragma unroll
        for (int i = 0; i < 2; i++)
            #pragma unroll
            for (int j = 0; j < 2; j++) {
                wmma::mma_sync(acc[i][j], af[0][i], bf[0][j], acc[i][j]);
                wmma::mma_sync(acc[i][j], af[0][i], bf[1][j], acc[i][j]);
                wmma::mma_sync(acc[i][j], af[1][i], bf[0][j], acc[i][j]);
            }
    }

    // ---- Store (C padded: no guards).
    #pragma unroll
    for (int i = 0; i < 2; i++)
        #pragma unroll
        for (int j = 0; j < 2; j++)
            wmma::store_matrix_sync(C + (size_t)(m0 + wm + i * 16) * DIM + wn + j * 16,
                                    acc[i][j], DIM, wmma::mem_row_major);
}

// ---------------------------------------------------------------------------
// Zero the aggregation buffer.
// ---------------------------------------------------------------------------
__global__ void zero_agg_kernel() {
    int i = blockIdx.x * blockDim.x + threadIdx.x;
    const int n4 = NN * DIM / 4;
    if (i < n4) ((float4*)g_agg)[i] = make_float4(0.f, 0.f, 0.f, 0.f);
}

// ---------------------------------------------------------------------------
// Edge kernel: one warp per edge; red.global.add.v4.f32 scatter.
// ---------------------------------------------------------------------------
__global__ __launch_bounds__(256) void edge_kernel(
    const int* __restrict__ src, const int* __restrict__ dst,
    const int* __restrict__ rel, const float* __restrict__ coeff)
{
    int e    = (blockIdx.x * blockDim.x + threadIdx.x) >> 5;
    int lane = threadIdx.x & 31;
    if (e >= NE) return;

    int s = __ldg(&src[e]);
    int d = __ldg(&dst[e]);
    int r = __ldg(&rel[e]);
    float4 c = *(const float4*)(coeff + r * 4);

    const float4* hb4 = (const float4*)g_hb;
    const size_t stride = (size_t)NN_PAD * 32;    // one basis block, in float4
    size_t base = (size_t)s * 32 + lane;

    float4 v0 = hb4[base];
    float4 v1 = hb4[base + stride];
    float4 v2 = hb4[base + 2 * stride];
    float4 v3 = hb4[base + 3 * stride];

    float4 m;
    m.x = fmaf(c.x, v0.x, fmaf(c.y, v1.x, fmaf(c.z, v2.x, c.w * v3.x)));
    m.y = fmaf(c.x, v0.y, fmaf(c.y, v1.y, fmaf(c.z, v2.y, c.w * v3.y)));
    m.z = fmaf(c.x, v0.z, fmaf(c.y, v1.z, fmaf(c.z, v2.z, c.w * v3.z)));
    m.w = fmaf(c.x, v0.w, fmaf(c.y, v1.w, fmaf(c.z, v2.w, c.w * v3.w)));

    float* outp = g_agg + (size_t)d * DIM + lane * 4;
    asm volatile("red.global.add.v4.f32 [%0], {%1, %2, %3, %4};"
                 :: "l"(outp), "f"(m.x), "f"(m.y), "f"(m.z), "f"(m.w) : "memory");
}

// ---------------------------------------------------------------------------
// Epilogue: out = relu(agg * norm + loop_message)
// ---------------------------------------------------------------------------
__global__ void final_kernel(const float* __restrict__ norm, float* __restrict__ out) {
    int i = blockIdx.x * blockDim.x + threadIdx.x;   // float4 index
    const int n4 = NN * DIM / 4;
    if (i >= n4) return;
    int node = i >> 5;
    float nm = __ldg(&norm[node]);
    float4 a = ((const float4*)g_agg)[i];
    float4 l = ((const float4*)g_loop)[i];
    float4 o;
    o.x = fmaxf(fmaf(a.x, nm, l.x), 0.f);
    o.y = fmaxf(fmaf(a.y, nm, l.y), 0.f);
    o.z = fmaxf(fmaf(a.z, nm, l.z), 0.f);
    o.w = fmaxf(fmaf(a.w, nm, l.w), 0.f);
    ((float4*)out)[i] = o;
}

// ---------------------------------------------------------------------------
extern "C" void kernel_launch(void* const* d_in, const int* in_sizes, int n_in,
                              void* d_out, int out_size) {
    const float* h     = (const float*)d_in[0];
    const float* norm  = (const float*)d_in[1];
    const int*   src   = (const int*)  d_in[2];
    const int*   dst   = (const int*)  d_in[3];
    const int*   rel   = (const int*)  d_in[4];
    const float* basis = (const float*)d_in[5];
    const float* coeff = (const float*)d_in[6];
    const float* loopw = (const float*)d_in[7];
    float* out = (float*)d_out;

    // Sticky attribute: set once, outside any captured work. Deterministic.
    static bool attr_done = false;
    if (!attr_done) {
        cudaFuncSetAttribute(gemm_wmma_kernel,
                             cudaFuncAttributeMaxDynamicSharedMemorySize, SM_TOTAL);
        attr_done = true;
    }

    split_h_kernel<<<(NN * DIM + 255) / 256, 256>>>(h);
    split_w_kernel<<<(NMAT * DIM * DIM + 255) / 256, 256>>>(basis, loopw);
    zero_agg_kernel<<<(NN * DIM / 4 + 255) / 256, 256>>>();

    dim3 gg(MTILES, NMAT);
    gemm_wmma_kernel<<<gg, 256, SM_TOTAL>>>();

    edge_kernel<<<(NE * 32) / 256, 256>>>(src, dst, rel, coeff);

    final_kernel<<<(NN * DIM / 4 + 255) / 256, 256>>>(norm, out);
}

// round 13
// speedup vs baseline: 1.1969x; 1.0183x over previous
#include <cuda_runtime.h>
#include <cuda_bf16.h>
#include <mma.h>
#include <cstdint>

using namespace nvcuda;

#define NN     50000
#define NN_PAD 50048                 // 391 * 128, padded so GEMM tiles need no guards
#define DIM    128
#define NB     4
#define NR     100
#define NE     800000
#define NMAT   5                     // 4 bases + loop
#define MTILES 782                   // NN_PAD / 64

// ---------------------------------------------------------------------------
// Device scratch (zero-initialized at module load; padded tails stay zero).
// ---------------------------------------------------------------------------
__device__ float g_hb[(size_t)NB * NN_PAD * DIM];        // 102.5 MB
__device__ float g_loop[(size_t)NN_PAD * DIM];           // 25.6 MB (self-loop msg)
__device__ float g_agg[(size_t)NN * DIM];                // 25.6 MB
__device__ __nv_bfloat16 g_h1[(size_t)NN_PAD * DIM];     // bf16 limbs of h
__device__ __nv_bfloat16 g_h2[(size_t)NN_PAD * DIM];
// W^T limbs: [mat][limb][n][k] bf16 (n-major, so wmma col_major B works)
__device__ __nv_bfloat16 g_wt[(size_t)NMAT * 2 * DIM * DIM];

// ---------------------------------------------------------------------------
// bf16x2 split of h:  x = b1 + b2 + O(2^-18 x)
// ---------------------------------------------------------------------------
__global__ void split_h_kernel(const float* __restrict__ h) {
    int i = blockIdx.x * blockDim.x + threadIdx.x;
    if (i >= NN * DIM) return;
    float x = h[i];
    __nv_bfloat16 b1 = __float2bfloat16(x);
    float r1 = x - __bfloat162float(b1);
    g_h1[i] = b1;
    g_h2[i] = __float2bfloat16(r1);
}

// bf16x2 split of W, transposed to [n][k]
__global__ void split_w_kernel(const float* __restrict__ basis,
                               const float* __restrict__ loopw) {
    int i = blockIdx.x * blockDim.x + threadIdx.x;   // over NMAT*DIM*DIM
    if (i >= NMAT * DIM * DIM) return;
    int mat = i / (DIM * DIM);
    int rem = i - mat * DIM * DIM;
    int n = rem / DIM, k = rem - (rem / DIM) * DIM;
    float x = (mat < NB) ? basis[(size_t)mat * DIM * DIM + k * DIM + n]
                         : loopw[k * DIM + n];
    __nv_bfloat16 b1 = __float2bfloat16(x);
    float r1 = x - __bfloat162float(b1);
    size_t base = (size_t)mat * 2 * DIM * DIM + (size_t)n * DIM + k;
    g_wt[base]             = b1;
    g_wt[base + DIM * DIM] = __float2bfloat16(r1);
}

// ---------------------------------------------------------------------------
// wmma bf16 GEMM: one CTA = 64x128 tile of C = h @ W.
// bf16x2 limbs, 3 significant products (a1w1, a1w2, a2w1), k-outer loop.
// 4 warps in a 2x2 grid; warp tile 32(M) x 64(N): 12 LDSM feed 24 wmma per
// k-step (MMA:LDSM = 2.0). 128 threads -> 256-reg budget, deep unroll, no
// spills. smem 104.4 KB -> 2 CTAs/SM.
// ---------------------------------------------------------------------------
#define SM_STRIDE 136                      // 128 + 8 bf16 pad
#define SM_A_LIMB (64 * SM_STRIDE)         // elements per A limb tile
#define SM_B_LIMB (128 * SM_STRIDE)        // elements per B limb tile
#define SM_TOTAL  ((2 * SM_A_LIMB + 2 * SM_B_LIMB) * 2)   // 104448 bytes

__global__ void __launch_bounds__(128, 2) gemm_wmma_kernel() {
    extern __shared__ __nv_bfloat16 smem[];
    __nv_bfloat16* As = smem;                   // [2][64][SM_STRIDE]
    __nv_bfloat16* Bs = smem + 2 * SM_A_LIMB;   // [2][128][SM_STRIDE]

    const int tid = threadIdx.x;
    const int wid = tid >> 5;
    const int mat = blockIdx.y;
    const int m0  = blockIdx.x * 64;
    float* C = (mat < NB) ? g_hb + (size_t)mat * NN_PAD * DIM : g_loop;

    // ---- Load A limbs (64 rows x 128 bf16 each); padded, no guards.
    {
        const __nv_bfloat16* hs[2] = { g_h1, g_h2 };
        #pragma unroll
        for (int s = 0; s < 2; s++) {
            const __nv_bfloat16* src = hs[s] + (size_t)m0 * DIM;
            __nv_bfloat16* dst = As + s * SM_A_LIMB;
            #pragma unroll
            for (int it = 0; it < 8; it++) {
                int idx = it * 128 + tid;         // 0..1023 16B chunks
                int row = idx >> 4;
                int c8  = (idx & 15) * 8;
                *(float4*)(dst + row * SM_STRIDE + c8) =
                    *(const float4*)(src + row * DIM + c8);
            }
        }
        // ---- Load B limbs (W^T, 128 n-rows x 128 k).
        const __nv_bfloat16* wb = g_wt + (size_t)mat * 2 * DIM * DIM;
        #pragma unroll
        for (int s = 0; s < 2; s++) {
            const __nv_bfloat16* src = wb + (size_t)s * DIM * DIM;
            __nv_bfloat16* dst = Bs + s * SM_B_LIMB;
            #pragma unroll
            for (int it = 0; it < 16; it++) {
                int idx = it * 128 + tid;         // 0..2047
                int row = idx >> 4;
                int c8  = (idx & 15) * 8;
                *(float4*)(dst + row * SM_STRIDE + c8) =
                    *(const float4*)(src + row * DIM + c8);
            }
        }
    }
    __syncthreads();

    const int wm = (wid >> 1) * 32;   // warp M origin (0, 32)
    const int wn = (wid & 1) * 64;    // warp N origin (0, 64)

    wmma::fragment<wmma::accumulator, 16, 16, 16, float> acc[2][4];
    #pragma unroll
    for (int i = 0; i < 2; i++)
        #pragma unroll
        for (int j = 0; j < 4; j++) wmma::fill_fragment(acc[i][j], 0.0f);

    #pragma unroll 4
    for (int k = 0; k < DIM; k += 16) {
        // A frags: [limb][m-sub]
        wmma::fragment<wmma::matrix_a, 16, 16, 16, __nv_bfloat16, wmma::row_major> af[2][2];
        #pragma unroll
        for (int s = 0; s < 2; s++) {
            wmma::load_matrix_sync(af[s][0], As + s * SM_A_LIMB + (wm     ) * SM_STRIDE + k, SM_STRIDE);
            wmma::load_matrix_sync(af[s][1], As + s * SM_A_LIMB + (wm + 16) * SM_STRIDE + k, SM_STRIDE);
        }
        // B frags: [limb][n-sub] (col_major: element (k, n) at ptr[n*ldm + k])
        wmma::fragment<wmma::matrix_b, 16, 16, 16, __nv_bfloat16, wmma::col_major> bf[2][4];
        #pragma unroll
        for (int s = 0; s < 2; s++)
            #pragma unroll
            for (int j = 0; j < 4; j++)
                wmma::load_matrix_sync(bf[s][j],
                    Bs + s * SM_B_LIMB + (wn + j * 16) * SM_STRIDE + k, SM_STRIDE);
        // 3 significant limb products per (mi, nj)
        #pragma unroll
        for (int i = 0; i < 2; i++)
            #pragma unroll
            for (int j = 0; j < 4; j++) {
                wmma::mma_sync(acc[i][j], af[0][i], bf[0][j], acc[i][j]);
                wmma::mma_sync(acc[i][j], af[0][i], bf[1][j], acc[i][j]);
                wmma::mma_sync(acc[i][j], af[1][i], bf[0][j], acc[i][j]);
            }
    }

    // ---- Store (C padded: no guards).
    #pragma unroll
    for (int i = 0; i < 2; i++)
        #pragma unroll
        for (int j = 0; j < 4; j++)
            wmma::store_matrix_sync(C + (size_t)(m0 + wm + i * 16) * DIM + wn + j * 16,
                                    acc[i][j], DIM, wmma::mem_row_major);
}

// ---------------------------------------------------------------------------
// Zero the aggregation buffer.
// ---------------------------------------------------------------------------
__global__ void zero_agg_kernel() {
    int i = blockIdx.x * blockDim.x + threadIdx.x;
    const int n4 = NN * DIM / 4;
    if (i < n4) ((float4*)g_agg)[i] = make_float4(0.f, 0.f, 0.f, 0.f);
}

// ---------------------------------------------------------------------------
// Edge kernel: one warp per edge; red.global.add.v4.f32 scatter.
// ---------------------------------------------------------------------------
__global__ __launch_bounds__(256) void edge_kernel(
    const int* __restrict__ src, const int* __restrict__ dst,
    const int* __restrict__ rel, const float* __restrict__ coeff)
{
    int e    = (blockIdx.x * blockDim.x + threadIdx.x) >> 5;
    int lane = threadIdx.x & 31;
    if (e >= NE) return;

    int s = __ldg(&src[e]);
    int d = __ldg(&dst[e]);
    int r = __ldg(&rel[e]);
    float4 c = *(const float4*)(coeff + r * 4);

    const float4* hb4 = (const float4*)g_hb;
    const size_t stride = (size_t)NN_PAD * 32;    // one basis block, in float4
    size_t base = (size_t)s * 32 + lane;

    float4 v0 = hb4[base];
    float4 v1 = hb4[base + stride];
    float4 v2 = hb4[base + 2 * stride];
    float4 v3 = hb4[base + 3 * stride];

    float4 m;
    m.x = fmaf(c.x, v0.x, fmaf(c.y, v1.x, fmaf(c.z, v2.x, c.w * v3.x)));
    m.y = fmaf(c.x, v0.y, fmaf(c.y, v1.y, fmaf(c.z, v2.y, c.w * v3.y)));
    m.z = fmaf(c.x, v0.z, fmaf(c.y, v1.z, fmaf(c.z, v2.z, c.w * v3.z)));
    m.w = fmaf(c.x, v0.w, fmaf(c.y, v1.w, fmaf(c.z, v2.w, c.w * v3.w)));

    float* outp = g_agg + (size_t)d * DIM + lane * 4;
    asm volatile("red.global.add.v4.f32 [%0], {%1, %2, %3, %4};"
                 :: "l"(outp), "f"(m.x), "f"(m.y), "f"(m.z), "f"(m.w) : "memory");
}

// ---------------------------------------------------------------------------
// Epilogue: out = relu(agg * norm + loop_message)
// ---------------------------------------------------------------------------
__global__ void final_kernel(const float* __restrict__ norm, float* __restrict__ out) {
    int i = blockIdx.x * blockDim.x + threadIdx.x;   // float4 index
    const int n4 = NN * DIM / 4;
    if (i >= n4) return;
    int node = i >> 5;
    float nm = __ldg(&norm[node]);
    float4 a = ((const float4*)g_agg)[i];
    float4 l = ((const float4*)g_loop)[i];
    float4 o;
    o.x = fmaxf(fmaf(a.x, nm, l.x), 0.f);
    o.y = fmaxf(fmaf(a.y, nm, l.y), 0.f);
    o.z = fmaxf(fmaf(a.z, nm, l.z), 0.f);
    o.w = fmaxf(fmaf(a.w, nm, l.w), 0.f);
    ((float4*)out)[i] = o;
}

// ---------------------------------------------------------------------------
extern "C" void kernel_launch(void* const* d_in, const int* in_sizes, int n_in,
                              void* d_out, int out_size) {
    const float* h     = (const float*)d_in[0];
    const float* norm  = (const float*)d_in[1];
    const int*   src   = (const int*)  d_in[2];
    const int*   dst   = (const int*)  d_in[3];
    const int*   rel   = (const int*)  d_in[4];
    const float* basis = (const float*)d_in[5];
    const float* coeff = (const float*)d_in[6];
    const float* loopw = (const float*)d_in[7];
    float* out = (float*)d_out;

    // Sticky attribute: set once, outside any captured work. Deterministic.
    static bool attr_done = false;
    if (!attr_done) {
        cudaFuncSetAttribute(gemm_wmma_kernel,
                             cudaFuncAttributeMaxDynamicSharedMemorySize, SM_TOTAL);
        attr_done = true;
    }

    split_h_kernel<<<(NN * DIM + 255) / 256, 256>>>(h);
    split_w_kernel<<<(NMAT * DIM * DIM + 255) / 256, 256>>>(basis, loopw);
    zero_agg_kernel<<<(NN * DIM / 4 + 255) / 256, 256>>>();

    dim3 gg(MTILES, NMAT);
    gemm_wmma_kernel<<<gg, 128, SM_TOTAL>>>();

    edge_kernel<<<(NE * 32) / 256, 256>>>(src, dst, rel, coeff);

    final_kernel<<<(NN * DIM / 4 + 255) / 256, 256>>>(norm, out);
}

// round 15
// speedup vs baseline: 1.2057x; 1.0073x over previous
#include <cuda_runtime.h>
#include <cuda_bf16.h>
#include <mma.h>
#include <cstdint>

using namespace nvcuda;

#define NN     50000
#define NN_PAD 50048                 // 391 * 128, padded so GEMM tiles need no guards
#define DIM    128
#define NB     4
#define NR     100
#define NE     800000
#define NMAT   5                     // 4 bases + loop
#define MTILES 782                   // NN_PAD / 64

// ---------------------------------------------------------------------------
// Device scratch (zero-initialized at load; padded tails stay zero).
// ---------------------------------------------------------------------------
__device__ float g_hb[(size_t)NB * NN_PAD * DIM];        // 102.5 MB
__device__ float g_loop[(size_t)NN_PAD * DIM];           // 25.6 MB (self-loop msg)
__device__ float g_agg[(size_t)NN * DIM];                // 25.6 MB
__device__ __nv_bfloat16 g_h1[(size_t)NN_PAD * DIM];     // bf16 limbs of h
__device__ __nv_bfloat16 g_h2[(size_t)NN_PAD * DIM];
__device__ __nv_bfloat16 g_wt[(size_t)NMAT * 2 * DIM * DIM]; // W^T limbs [mat][limb][n][k]
// CSR-by-src scratch
__device__ int g_cnt[NN];            // histogram, then scatter cursor
__device__ int g_rowptr[NN + 1];
__device__ int g_epack[NE];          // dst | rel << 17

// ---------------------------------------------------------------------------
// bf16x2 split of h
// ---------------------------------------------------------------------------
__global__ void split_h_kernel(const float* __restrict__ h) {
    int i = blockIdx.x * blockDim.x + threadIdx.x;
    if (i >= NN * DIM) return;
    float x = h[i];
    __nv_bfloat16 b1 = __float2bfloat16(x);
    float r1 = x - __bfloat162float(b1);
    g_h1[i] = b1;
    g_h2[i] = __float2bfloat16(r1);
}

// bf16x2 split of W, transposed to [n][k]
__global__ void split_w_kernel(const float* __restrict__ basis,
                               const float* __restrict__ loopw) {
    int i = blockIdx.x * blockDim.x + threadIdx.x;
    if (i >= NMAT * DIM * DIM) return;
    int mat = i / (DIM * DIM);
    int rem = i - mat * DIM * DIM;
    int n = rem / DIM, k = rem - (rem / DIM) * DIM;
    float x = (mat < NB) ? basis[(size_t)mat * DIM * DIM + k * DIM + n]
                         : loopw[k * DIM + n];
    __nv_bfloat16 b1 = __float2bfloat16(x);
    float r1 = x - __bfloat162float(b1);
    size_t base = (size_t)mat * 2 * DIM * DIM + (size_t)n * DIM + k;
    g_wt[base]             = b1;
    g_wt[base + DIM * DIM] = __float2bfloat16(r1);
}

// ---------------------------------------------------------------------------
// wmma bf16 GEMM (unchanged from R13): CTA = 64x128, 4 warps 32x64, K resident.
// ---------------------------------------------------------------------------
#define SM_STRIDE 136
#define SM_A_LIMB (64 * SM_STRIDE)
#define SM_B_LIMB (128 * SM_STRIDE)
#define SM_TOTAL  ((2 * SM_A_LIMB + 2 * SM_B_LIMB) * 2)   // 104448 bytes

__global__ void __launch_bounds__(128, 2) gemm_wmma_kernel() {
    extern __shared__ __nv_bfloat16 smem[];
    __nv_bfloat16* As = smem;
    __nv_bfloat16* Bs = smem + 2 * SM_A_LIMB;

    const int tid = threadIdx.x;
    const int wid = tid >> 5;
    const int mat = blockIdx.y;
    const int m0  = blockIdx.x * 64;
    float* C = (mat < NB) ? g_hb + (size_t)mat * NN_PAD * DIM : g_loop;

    {
        const __nv_bfloat16* hs[2] = { g_h1, g_h2 };
        #pragma unroll
        for (int s = 0; s < 2; s++) {
            const __nv_bfloat16* src = hs[s] + (size_t)m0 * DIM;
            __nv_bfloat16* dst = As + s * SM_A_LIMB;
            #pragma unroll
            for (int it = 0; it < 8; it++) {
                int idx = it * 128 + tid;
                int row = idx >> 4;
                int c8  = (idx & 15) * 8;
                *(float4*)(dst + row * SM_STRIDE + c8) =
                    *(const float4*)(src + row * DIM + c8);
            }
        }
        const __nv_bfloat16* wb = g_wt + (size_t)mat * 2 * DIM * DIM;
        #pragma unroll
        for (int s = 0; s < 2; s++) {
            const __nv_bfloat16* src = wb + (size_t)s * DIM * DIM;
            __nv_bfloat16* dst = Bs + s * SM_B_LIMB;
            #pragma unroll
            for (int it = 0; it < 16; it++) {
                int idx = it * 128 + tid;
                int row = idx >> 4;
                int c8  = (idx & 15) * 8;
                *(float4*)(dst + row * SM_STRIDE + c8) =
                    *(const float4*)(src + row * DIM + c8);
            }
        }
    }
    __syncthreads();

    const int wm = (wid >> 1) * 32;
    const int wn = (wid & 1) * 64;

    wmma::fragment<wmma::accumulator, 16, 16, 16, float> acc[2][4];
    #pragma unroll
    for (int i = 0; i < 2; i++)
        #pragma unroll
        for (int j = 0; j < 4; j++) wmma::fill_fragment(acc[i][j], 0.0f);

    #pragma unroll 4
    for (int k = 0; k < DIM; k += 16) {
        wmma::fragment<wmma::matrix_a, 16, 16, 16, __nv_bfloat16, wmma::row_major> af[2][2];
        #pragma unroll
        for (int s = 0; s < 2; s++) {
            wmma::load_matrix_sync(af[s][0], As + s * SM_A_LIMB + (wm     ) * SM_STRIDE + k, SM_STRIDE);
            wmma::load_matrix_sync(af[s][1], As + s * SM_A_LIMB + (wm + 16) * SM_STRIDE + k, SM_STRIDE);
        }
        wmma::fragment<wmma::matrix_b, 16, 16, 16, __nv_bfloat16, wmma::col_major> bf[2][4];
        #pragma unroll
        for (int s = 0; s < 2; s++)
            #pragma unroll
            for (int j = 0; j < 4; j++)
                wmma::load_matrix_sync(bf[s][j],
                    Bs + s * SM_B_LIMB + (wn + j * 16) * SM_STRIDE + k, SM_STRIDE);
        #pragma unroll
        for (int i = 0; i < 2; i++)
            #pragma unroll
            for (int j = 0; j < 4; j++) {
                wmma::mma_sync(acc[i][j], af[0][i], bf[0][j], acc[i][j]);
                wmma::mma_sync(acc[i][j], af[0][i], bf[1][j], acc[i][j]);
                wmma::mma_sync(acc[i][j], af[1][i], bf[0][j], acc[i][j]);
            }
    }

    #pragma unroll
    for (int i = 0; i < 2; i++)
        #pragma unroll
        for (int j = 0; j < 4; j++)
            wmma::store_matrix_sync(C + (size_t)(m0 + wm + i * 16) * DIM + wn + j * 16,
                                    acc[i][j], DIM, wmma::mem_row_major);
}

// ---------------------------------------------------------------------------
// Zero agg + CSR histogram counters.
// ---------------------------------------------------------------------------
__global__ void zero_kernel() {
    int i = blockIdx.x * blockDim.x + threadIdx.x;
    const int n4 = NN * DIM / 4;
    if (i < n4) ((float4*)g_agg)[i] = make_float4(0.f, 0.f, 0.f, 0.f);
    if (i < NN) g_cnt[i] = 0;
}

// ---------------------------------------------------------------------------
// CSR build: histogram -> single-CTA scan -> scatter of packed (dst, rel).
// ---------------------------------------------------------------------------
__global__ void hist_kernel(const int* __restrict__ src) {
    int e = blockIdx.x * blockDim.x + threadIdx.x;
    if (e < NE) atomicAdd(&g_cnt[src[e]], 1);
}

__global__ void scan_kernel() {      // 1 CTA, 1024 threads
    __shared__ int psum[1024];
    const int t = threadIdx.x;
    const int CH = (NN + 1023) / 1024;   // 49
    int beg = t * CH;
    int end = beg + CH; if (end > NN) end = NN;
    int s = 0;
    for (int i = beg; i < end; i++) s += g_cnt[i];
    psum[t] = s;
    __syncthreads();
    for (int off = 1; off < 1024; off <<= 1) {
        int v = (t >= off) ? psum[t - off] : 0;
        __syncthreads();
        psum[t] += v;
        __syncthreads();
    }
    int base = (t > 0) ? psum[t - 1] : 0;
    for (int i = beg; i < end; i++) {
        int c = g_cnt[i];
        g_rowptr[i] = base;
        g_cnt[i]    = base;          // becomes scatter cursor
        base += c;
    }
    if (t == 1023) g_rowptr[NN] = psum[1023];
}

__global__ void scatter_kernel(const int* __restrict__ src,
                               const int* __restrict__ dst,
                               const int* __restrict__ rel) {
    int e = blockIdx.x * blockDim.x + threadIdx.x;
    if (e >= NE) return;
    int pos = atomicAdd(&g_cnt[src[e]], 1);
    g_epack[pos] = dst[e] | (rel[e] << 17);
}

// ---------------------------------------------------------------------------
// Edge kernel (CSR): one warp per SOURCE node. hb rows read once (coalesced),
// then per-edge: 4B packed read + L1-hit coeff + red.v4 scatter.
// ---------------------------------------------------------------------------
__global__ __launch_bounds__(256) void edge_csr_kernel(const float* __restrict__ coeff) {
    int n    = (blockIdx.x * blockDim.x + threadIdx.x) >> 5;
    int lane = threadIdx.x & 31;
    if (n >= NN) return;

    int beg = __ldg(&g_rowptr[n]);
    int end = __ldg(&g_rowptr[n + 1]);
    if (beg == end) return;

    const float4* hb4 = (const float4*)g_hb;
    const size_t stride = (size_t)NN_PAD * 32;
    size_t base = (size_t)n * 32 + lane;

    float4 v0 = hb4[base];
    float4 v1 = hb4[base + stride];
    float4 v2 = hb4[base + 2 * stride];
    float4 v3 = hb4[base + 3 * stride];

    for (int e = beg; e < end; e++) {
        int p = __ldg(&g_epack[e]);          // warp-uniform broadcast
        int d = p & 131071;
        int r = p >> 17;
        float4 c = *(const float4*)(coeff + r * 4);   // L1-resident (1.6 KB)

        float4 m;
        m.x = fmaf(c.x, v0.x, fmaf(c.y, v1.x, fmaf(c.z, v2.x, c.w * v3.x)));
        m.y = fmaf(c.x, v0.y, fmaf(c.y, v1.y, fmaf(c.z, v2.y, c.w * v3.y)));
        m.z = fmaf(c.x, v0.z, fmaf(c.y, v1.z, fmaf(c.z, v2.z, c.w * v3.z)));
        m.w = fmaf(c.x, v0.w, fmaf(c.y, v1.w, fmaf(c.z, v2.w, c.w * v3.w)));

        float* outp = g_agg + (size_t)d * DIM + lane * 4;
        asm volatile("red.global.add.v4.f32 [%0], {%1, %2, %3, %4};"
                     :: "l"(outp), "f"(m.x), "f"(m.y), "f"(m.z), "f"(m.w) : "memory");
    }
}

// ---------------------------------------------------------------------------
// Epilogue: out = relu(agg * norm + loop_message)
// ---------------------------------------------------------------------------
__global__ void final_kernel(const float* __restrict__ norm, float* __restrict__ out) {
    int i = blockIdx.x * blockDim.x + threadIdx.x;
    const int n4 = NN * DIM / 4;
    if (i >= n4) return;
    int node = i >> 5;
    float nm = __ldg(&norm[node]);
    float4 a = ((const float4*)g_agg)[i];
    float4 l = ((const float4*)g_loop)[i];
    float4 o;
    o.x = fmaxf(fmaf(a.x, nm, l.x), 0.f);
    o.y = fmaxf(fmaf(a.y, nm, l.y), 0.f);
    o.z = fmaxf(fmaf(a.z, nm, l.z), 0.f);
    o.w = fmaxf(fmaf(a.w, nm, l.w), 0.f);
    ((float4*)out)[i] = o;
}

// ---------------------------------------------------------------------------
extern "C" void kernel_launch(void* const* d_in, const int* in_sizes, int n_in,
                              void* d_out, int out_size) {
    const float* h     = (const float*)d_in[0];
    const float* norm  = (const float*)d_in[1];
    const int*   src   = (const int*)  d_in[2];
    const int*   dst   = (const int*)  d_in[3];
    const int*   rel   = (const int*)  d_in[4];
    const float* basis = (const float*)d_in[5];
    const float* coeff = (const float*)d_in[6];
    const float* loopw = (const float*)d_in[7];
    float* out = (float*)d_out;

    static bool attr_done = false;
    if (!attr_done) {
        cudaFuncSetAttribute(gemm_wmma_kernel,
                             cudaFuncAttributeMaxDynamicSharedMemorySize, SM_TOTAL);
        attr_done = true;
    }

    // CSR build + precision split (independent of GEMM output)
    zero_kernel<<<(NN * DIM / 4 + 255) / 256, 256>>>();
    hist_kernel<<<(NE + 255) / 256, 256>>>(src);
    scan_kernel<<<1, 1024>>>();
    scatter_kernel<<<(NE + 255) / 256, 256>>>(src, dst, rel);

    split_h_kernel<<<(NN * DIM + 255) / 256, 256>>>(h);
    split_w_kernel<<<(NMAT * DIM * DIM + 255) / 256, 256>>>(basis, loopw);

    dim3 gg(MTILES, NMAT);
    gemm_wmma_kernel<<<gg, 128, SM_TOTAL>>>();

    edge_csr_kernel<<<(NN * 32 + 255) / 256, 256>>>(coeff);

    final_kernel<<<(NN * DIM / 4 + 255) / 256, 256>>>(norm, out);
}

// round 16
// speedup vs baseline: 1.2395x; 1.0280x over previous
#include <cuda_runtime.h>
#include <cuda_bf16.h>
#include <mma.h>
#include <cstdint>

using namespace nvcuda;

#define NN     50000
#define NN_PAD 50048                 // 391 * 128
#define DIM    128
#define KT     512                   // NB * DIM: K of the fused t-GEMM
#define NB     4
#define NR     100
#define NE     800000
#define MTILES 782                   // NN_PAD / 64

// ---------------------------------------------------------------------------
// Device scratch (zero-initialized at load; padded/untouched rows stay zero).
// ---------------------------------------------------------------------------
__device__ float g_agg[(size_t)NN_PAD * DIM];            // t @ basis GEMM output
__device__ float g_loop[(size_t)NN_PAD * DIM];           // self-loop message
__device__ __nv_bfloat16 g_h1[(size_t)NN_PAD * DIM];     // bf16 limbs of h
__device__ __nv_bfloat16 g_h2[(size_t)NN_PAD * DIM];
__device__ __nv_bfloat16 g_t1[(size_t)NN_PAD * KT];      // bf16 limbs of t (51.2 MB)
__device__ __nv_bfloat16 g_t2[(size_t)NN_PAD * KT];
__device__ __nv_bfloat16 g_wt[(size_t)5 * 2 * DIM * DIM]; // W^T limbs [mat][limb][n][k]
// CSR-by-dst scratch
__device__ int g_cnt[NN];
__device__ int g_rowptr[NN + 1];
__device__ int g_epack[NE];          // src | rel << 17

// ---------------------------------------------------------------------------
// bf16x2 split of h (for the loop GEMM)
// ---------------------------------------------------------------------------
__global__ void split_h_kernel(const float* __restrict__ h) {
    int i = blockIdx.x * blockDim.x + threadIdx.x;
    if (i >= NN * DIM) return;
    float x = h[i];
    __nv_bfloat16 b1 = __float2bfloat16(x);
    float r1 = x - __bfloat162float(b1);
    g_h1[i] = b1;
    g_h2[i] = __float2bfloat16(r1);
}

// bf16x2 split of W, transposed to [n][k]; mats 0..3 = bases, 4 = loop
__global__ void split_w_kernel(const float* __restrict__ basis,
                               const float* __restrict__ loopw) {
    int i = blockIdx.x * blockDim.x + threadIdx.x;
    if (i >= 5 * DIM * DIM) return;
    int mat = i / (DIM * DIM);
    int rem = i - mat * DIM * DIM;
    int n = rem / DIM, k = rem - (rem / DIM) * DIM;
    float x = (mat < NB) ? basis[(size_t)mat * DIM * DIM + k * DIM + n]
                         : loopw[k * DIM + n];
    __nv_bfloat16 b1 = __float2bfloat16(x);
    float r1 = x - __bfloat162float(b1);
    size_t base = (size_t)mat * 2 * DIM * DIM + (size_t)n * DIM + k;
    g_wt[base]             = b1;
    g_wt[base + DIM * DIM] = __float2bfloat16(r1);
}

// ---------------------------------------------------------------------------
// CSR build (by DST): zero counters -> histogram -> 1-CTA scan -> scatter.
// ---------------------------------------------------------------------------
__global__ void zero_cnt_kernel() {
    int i = blockIdx.x * blockDim.x + threadIdx.x;
    if (i < NN) g_cnt[i] = 0;
}

__global__ void hist_kernel(const int* __restrict__ dst) {
    int e = blockIdx.x * blockDim.x + threadIdx.x;
    if (e < NE) atomicAdd(&g_cnt[dst[e]], 1);
}

__global__ void scan_kernel() {      // 1 CTA, 1024 threads
    __shared__ int psum[1024];
    const int t = threadIdx.x;
    const int CH = (NN + 1023) / 1024;   // 49
    int beg = t * CH;
    int end = beg + CH; if (end > NN) end = NN;
    int s = 0;
    for (int i = beg; i < end; i++) s += g_cnt[i];
    psum[t] = s;
    __syncthreads();
    for (int off = 1; off < 1024; off <<= 1) {
        int v = (t >= off) ? psum[t - off] : 0;
        __syncthreads();
        psum[t] += v;
        __syncthreads();
    }
    int base = (t > 0) ? psum[t - 1] : 0;
    for (int i = beg; i < end; i++) {
        int c = g_cnt[i];
        g_rowptr[i] = base;
        g_cnt[i]    = base;          // becomes scatter cursor
        base += c;
    }
    if (t == 1023) g_rowptr[NN] = psum[1023];
}

__global__ void scatter_kernel(const int* __restrict__ src,
                               const int* __restrict__ dst,
                               const int* __restrict__ rel) {
    int e = blockIdx.x * blockDim.x + threadIdx.x;
    if (e >= NE) return;
    int pos = atomicAdd(&g_cnt[dst[e]], 1);
    g_epack[pos] = src[e] | (rel[e] << 17);
}

// ---------------------------------------------------------------------------
// Edge kernel: one warp per DST node. Accumulate t[n][b][:] in registers
// (16 fp32/lane), NO atomics; emit t as bf16x2 limbs directly.
// ---------------------------------------------------------------------------
__global__ __launch_bounds__(256) void edge_t_kernel(const float* __restrict__ h,
                                                     const float* __restrict__ coeff) {
    int n    = (blockIdx.x * blockDim.x + threadIdx.x) >> 5;
    int lane = threadIdx.x & 31;
    if (n >= NN) return;

    const int beg = __ldg(&g_rowptr[n]);
    const int end = __ldg(&g_rowptr[n + 1]);

    float4 acc[NB];
    #pragma unroll
    for (int b = 0; b < NB; b++) acc[b] = make_float4(0.f, 0.f, 0.f, 0.f);

    const float4* h4 = (const float4*)h;

    int e = beg;
    // Pairwise unroll: two independent gathers in flight (MLP=2).
    for (; e + 1 < end; e += 2) {
        int p0 = __ldg(&g_epack[e]);
        int p1 = __ldg(&g_epack[e + 1]);
        float4 v0 = h4[(size_t)(p0 & 131071) * 32 + lane];
        float4 v1 = h4[(size_t)(p1 & 131071) * 32 + lane];
        float4 c0 = *(const float4*)(coeff + (p0 >> 17) * 4);
        float4 c1 = *(const float4*)(coeff + (p1 >> 17) * 4);
        #pragma unroll
        for (int b = 0; b < NB; b++) {
            float cb0 = (&c0.x)[b];
            acc[b].x = fmaf(cb0, v0.x, acc[b].x);
            acc[b].y = fmaf(cb0, v0.y, acc[b].y);
            acc[b].z = fmaf(cb0, v0.z, acc[b].z);
            acc[b].w = fmaf(cb0, v0.w, acc[b].w);
            float cb1 = (&c1.x)[b];
            acc[b].x = fmaf(cb1, v1.x, acc[b].x);
            acc[b].y = fmaf(cb1, v1.y, acc[b].y);
            acc[b].z = fmaf(cb1, v1.z, acc[b].z);
            acc[b].w = fmaf(cb1, v1.w, acc[b].w);
        }
    }
    if (e < end) {
        int p0 = __ldg(&g_epack[e]);
        float4 v0 = h4[(size_t)(p0 & 131071) * 32 + lane];
        float4 c0 = *(const float4*)(coeff + (p0 >> 17) * 4);
        #pragma unroll
        for (int b = 0; b < NB; b++) {
            float cb0 = (&c0.x)[b];
            acc[b].x = fmaf(cb0, v0.x, acc[b].x);
            acc[b].y = fmaf(cb0, v0.y, acc[b].y);
            acc[b].z = fmaf(cb0, v0.z, acc[b].z);
            acc[b].w = fmaf(cb0, v0.w, acc[b].w);
        }
    }

    // Split to bf16 limbs and store (always store: zero rows stay correct).
    #pragma unroll
    for (int b = 0; b < NB; b++) {
        size_t o = (size_t)n * KT + b * DIM + lane * 4;
        float4 a = acc[b];
        __nv_bfloat16 x1 = __float2bfloat16(a.x);
        __nv_bfloat16 y1 = __float2bfloat16(a.y);
        __nv_bfloat16 z1 = __float2bfloat16(a.z);
        __nv_bfloat16 w1 = __float2bfloat16(a.w);
        ((__nv_bfloat162*)(g_t1 + o))[0] = __halves2bfloat162(x1, y1);
        ((__nv_bfloat162*)(g_t1 + o))[1] = __halves2bfloat162(z1, w1);
        ((__nv_bfloat162*)(g_t2 + o))[0] = __halves2bfloat162(
            __float2bfloat16(a.x - __bfloat162float(x1)),
            __float2bfloat16(a.y - __bfloat162float(y1)));
        ((__nv_bfloat162*)(g_t2 + o))[1] = __halves2bfloat162(
            __float2bfloat16(a.z - __bfloat162float(z1)),
            __float2bfloat16(a.w - __bfloat162float(w1)));
    }
}

// ---------------------------------------------------------------------------
// wmma bf16 GEMM with K-chunk loop.
//   blockIdx.y == 0: agg = t @ stacked-basis (K=512, 4 chunks, C=g_agg)
//   blockIdx.y == 1: loop = h @ loop_w       (K=128, 1 chunk,  C=g_loop)
// CTA = 64x128 tile; 4 warps, warp tile 32x64; limbs a1w1+a1w2+a2w1.
// ---------------------------------------------------------------------------
#define SM_STRIDE 136
#define SM_A_LIMB (64 * SM_STRIDE)
#define SM_B_LIMB (128 * SM_STRIDE)
#define SM_TOTAL  ((2 * SM_A_LIMB + 2 * SM_B_LIMB) * 2)   // 104448 bytes

__global__ void __launch_bounds__(128, 2) gemm_wmma_kernel() {
    extern __shared__ __nv_bfloat16 smem[];
    __nv_bfloat16* As = smem;
    __nv_bfloat16* Bs = smem + 2 * SM_A_LIMB;

    const int tid = threadIdx.x;
    const int wid = tid >> 5;
    const int mat = blockIdx.y;
    const int m0  = blockIdx.x * 64;

    const int nchunks          = (mat == 0) ? NB : 1;
    const int strideA          = (mat == 0) ? KT : DIM;
    const __nv_bfloat16* A1    = (mat == 0) ? g_t1 : g_h1;
    const __nv_bfloat16* A2    = (mat == 0) ? g_t2 : g_h2;
    const int wmat0            = (mat == 0) ? 0 : NB;     // which W^T block
    float* C                   = (mat == 0) ? g_agg : g_loop;

    const int wm = (wid >> 1) * 32;
    const int wn = (wid & 1) * 64;

    wmma::fragment<wmma::accumulator, 16, 16, 16, float> acc[2][4];
    #pragma unroll
    for (int i = 0; i < 2; i++)
        #pragma unroll
        for (int j = 0; j < 4; j++) wmma::fill_fragment(acc[i][j], 0.0f);

    for (int kc = 0; kc < nchunks; kc++) {
        // ---- Stage A limbs (64 x 128) and B limbs (128 x 128) for chunk kc.
        {
            const __nv_bfloat16* a1 = A1 + (size_t)m0 * strideA + kc * DIM;
            const __nv_bfloat16* a2 = A2 + (size_t)m0 * strideA + kc * DIM;
            #pragma unroll
            for (int it = 0; it < 8; it++) {
                int idx = it * 128 + tid;          // 0..1023 16B chunks
                int row = idx >> 4;
                int c8  = (idx & 15) * 8;
                *(float4*)(As + row * SM_STRIDE + c8) =
                    *(const float4*)(a1 + (size_t)row * strideA + c8);
                *(float4*)(As + SM_A_LIMB + row * SM_STRIDE + c8) =
                    *(const float4*)(a2 + (size_t)row * strideA + c8);
            }
            const __nv_bfloat16* wb = g_wt + (size_t)(wmat0 + kc) * 2 * DIM * DIM;
            #pragma unroll
            for (int it = 0; it < 16; it++) {
                int idx = it * 128 + tid;          // 0..2047
                int row = idx >> 4;
                int c8  = (idx & 15) * 8;
                *(float4*)(Bs + row * SM_STRIDE + c8) =
                    *(const float4*)(wb + (size_t)row * DIM + c8);
                *(float4*)(Bs + SM_B_LIMB + row * SM_STRIDE + c8) =
                    *(const float4*)(wb + DIM * DIM + (size_t)row * DIM + c8);
            }
        }
        __syncthreads();

        #pragma unroll 4
        for (int k = 0; k < DIM; k += 16) {
            wmma::fragment<wmma::matrix_a, 16, 16, 16, __nv_bfloat16, wmma::row_major> af[2][2];
            #pragma unroll
            for (int s = 0; s < 2; s++) {
                wmma::load_matrix_sync(af[s][0], As + s * SM_A_LIMB + (wm     ) * SM_STRIDE + k, SM_STRIDE);
                wmma::load_matrix_sync(af[s][1], As + s * SM_A_LIMB + (wm + 16) * SM_STRIDE + k, SM_STRIDE);
            }
            wmma::fragment<wmma::matrix_b, 16, 16, 16, __nv_bfloat16, wmma::col_major> bf[2][4];
            #pragma unroll
            for (int s = 0; s < 2; s++)
                #pragma unroll
                for (int j = 0; j < 4; j++)
                    wmma::load_matrix_sync(bf[s][j],
                        Bs + s * SM_B_LIMB + (wn + j * 16) * SM_STRIDE + k, SM_STRIDE);
            #pragma unroll
            for (int i = 0; i < 2; i++)
                #pragma unroll
                for (int j = 0; j < 4; j++) {
                    wmma::mma_sync(acc[i][j], af[0][i], bf[0][j], acc[i][j]);
                    wmma::mma_sync(acc[i][j], af[0][i], bf[1][j], acc[i][j]);
                    wmma::mma_sync(acc[i][j], af[1][i], bf[0][j], acc[i][j]);
                }
        }
        __syncthreads();
    }

    #pragma unroll
    for (int i = 0; i < 2; i++)
        #pragma unroll
        for (int j = 0; j < 4; j++)
            wmma::store_matrix_sync(C + (size_t)(m0 + wm + i * 16) * DIM + wn + j * 16,
                                    acc[i][j], DIM, wmma::mem_row_major);
}

// ---------------------------------------------------------------------------
// Epilogue: out = relu(agg * norm + loop_message)
// ---------------------------------------------------------------------------
__global__ void final_kernel(const float* __restrict__ norm, float* __restrict__ out) {
    int i = blockIdx.x * blockDim.x + threadIdx.x;
    const int n4 = NN * DIM / 4;
    if (i >= n4) return;
    int node = i >> 5;
    float nm = __ldg(&norm[node]);
    float4 a = ((const float4*)g_agg)[i];
    float4 l = ((const float4*)g_loop)[i];
    float4 o;
    o.x = fmaxf(fmaf(a.x, nm, l.x), 0.f);
    o.y = fmaxf(fmaf(a.y, nm, l.y), 0.f);
    o.z = fmaxf(fmaf(a.z, nm, l.z), 0.f);
    o.w = fmaxf(fmaf(a.w, nm, l.w), 0.f);
    ((float4*)out)[i] = o;
}

// ---------------------------------------------------------------------------
extern "C" void kernel_launch(void* const* d_in, const int* in_sizes, int n_in,
                              void* d_out, int out_size) {
    const float* h     = (const float*)d_in[0];
    const float* norm  = (const float*)d_in[1];
    const int*   src   = (const int*)  d_in[2];
    const int*   dst   = (const int*)  d_in[3];
    const int*   rel   = (const int*)  d_in[4];
    const float* basis = (const float*)d_in[5];
    const float* coeff = (const float*)d_in[6];
    const float* loopw = (const float*)d_in[7];
    float* out = (float*)d_out;

    static bool attr_done = false;
    if (!attr_done) {
        cudaFuncSetAttribute(gemm_wmma_kernel,
                             cudaFuncAttributeMaxDynamicSharedMemorySize, SM_TOTAL);
        attr_done = true;
    }

    // CSR by dst
    zero_cnt_kernel<<<(NN + 255) / 256, 256>>>();
    hist_kernel<<<(NE + 255) / 256, 256>>>(dst);
    scan_kernel<<<1, 1024>>>();
    scatter_kernel<<<(NE + 255) / 256, 256>>>(src, dst, rel);

    split_h_kernel<<<(NN * DIM + 255) / 256, 256>>>(h);
    split_w_kernel<<<(5 * DIM * DIM + 255) / 256, 256>>>(basis, loopw);

    // Input-space aggregation by dst (no atomics), emits t limbs.
    edge_t_kernel<<<(NN * 32 + 255) / 256, 256>>>(h, coeff);

    // Fused t@basis (K=512) + loop GEMM.
    dim3 gg(MTILES, 2);
    gemm_wmma_kernel<<<gg, 128, SM_TOTAL>>>();

    final_kernel<<<(NN * DIM / 4 + 255) / 256, 256>>>(norm, out);
}